// round 10
// baseline (speedup 1.0000x reference)
#include <cuda_runtime.h>
#include <cstdint>

// Problem constants
#define NROWS 65536
#define DDIM  1024
#define KC    256

// ---------------- device scratch (no allocations allowed) ----------------
__device__ float g_U[(size_t)NROWS * KC];
__device__ float g_V[(size_t)NROWS * KC];
__device__ float g_Z[(size_t)NROWS * KC];
__device__ float g_Wr[(size_t)DDIM * DDIM];   // rna-tf32-rounded W
__device__ float g_Hpart[64 * KC * KC];
__device__ float g_H[KC * KC];
__device__ float g_cspU[256 * KC];
__device__ float g_cspV[256 * KC];
__device__ float g_pdot[KC];
__device__ float g_D;

// ---------------- helpers ----------------
__device__ __forceinline__ unsigned f2tf(float f) {
    unsigned u;
    asm("cvt.rna.tf32.f32 %0, %1;" : "=r"(u) : "f"(f));
    return u;
}
__device__ __forceinline__ float f2tf_f(float f) { return __uint_as_float(f2tf(f)); }
__device__ __forceinline__ void cpa16(float* s, const float* g) {
    unsigned sa = (unsigned)__cvta_generic_to_shared(s);
    asm volatile("cp.async.cg.shared.global [%0], [%1], 16;" :: "r"(sa), "l"(g));
}
__device__ __forceinline__ void cpcommit() { asm volatile("cp.async.commit_group;"); }
template <int N> __device__ __forceinline__ void cpwait() {
    asm volatile("cp.async.wait_group %0;" :: "n"(N));
}
__device__ __forceinline__ void mma8(float* c, const unsigned* a, const unsigned* b) {
    asm volatile(
        "mma.sync.aligned.m16n8k8.row.col.f32.tf32.tf32.f32 "
        "{%0,%1,%2,%3},{%4,%5,%6,%7},{%8,%9},{%0,%1,%2,%3};"
        : "+f"(c[0]), "+f"(c[1]), "+f"(c[2]), "+f"(c[3])
        : "r"(a[0]), "r"(a[1]), "r"(a[2]), "r"(a[3]), "r"(b[0]), "r"(b[1]));
}

// ---------------- prepass: W -> rna-tf32-rounded g_Wr ----------------
__global__ void round_W_k(const float* __restrict__ W) {
    int i = (blockIdx.x * 256 + threadIdx.x) * 4;
    float4 v = *(const float4*)(W + i);
    v.x = f2tf_f(v.x); v.y = f2tf_f(v.y); v.z = f2tf_f(v.z); v.w = f2tf_f(v.w);
    *(float4*)(g_Wr + i) = v;
}
__global__ void dummy_k() {}

// ================= NT GEMM: C[M,N] = A[M,KA] * B[N,KA]^T =================
// CTA tile 128x128, 8 warps (2x4), warp tile 64x32. 3-stage cp.async,
// one __syncthreads per K-chunk, single-buffered fragments (4 warps/SMSP
// at 2 CTAs/SM cover latency). Low regs (<=128) so 2 CTAs co-reside.
// CVT_A=1: cvt.rna.tf32 on A fragments (A raw fp32). B always pre-rounded.
// EPI=0: bias+relu; bx 0..5 -> U/V/Z (tf32-rounded), bx 6..7 -> out[:,256:512].
// EPI=1: res = U * H^T * g_D -> out[:, 0:256].
template <int KA, int CVT_A, int EPI>
__global__ __launch_bounds__(256, 2)
void gemm_nt(const float* __restrict__ Ain, const float* __restrict__ bias,
             float* __restrict__ out) {
    extern __shared__ float sm[];
    const int ST = 2 * 128 * 36;             // A+B floats per stage

    const float* A = (EPI == 1) ? g_U : Ain;
    const float* B = (EPI == 1) ? g_H : g_Wr;

    const int m0 = blockIdx.y * 128, n0 = blockIdx.x * 128;
    const int tid = threadIdx.x;
    const int warp = tid >> 5, lane = tid & 31, g = lane >> 2, tg = lane & 3;
    const int wm = (warp >> 2) * 64, wn = (warp & 3) * 32;

    float acc[4][4][4];
#pragma unroll
    for (int i = 0; i < 4; i++)
#pragma unroll
        for (int j = 0; j < 4; j++)
#pragma unroll
            for (int c = 0; c < 4; c++) acc[i][j][c] = 0.f;

    const int NK = KA / 32;

    auto load_stage = [&](int s) {
        float* sA = sm + (s % 3) * ST;
        float* sB = sA + 128 * 36;
        const int k0 = s * 32;
#pragma unroll
        for (int i = 0; i < 4; i++) {
            int idx = tid + i * 256;
            int row = idx >> 3, kv = (idx & 7) * 4;
            cpa16(sA + row * 36 + kv, A + (size_t)(m0 + row) * KA + k0 + kv);
            cpa16(sB + row * 36 + kv, B + (size_t)(n0 + row) * KA + k0 + kv);
        }
        cpcommit();
    };

    load_stage(0);
    load_stage(1);

    for (int kt = 0; kt < NK; kt++) {
        if (kt + 1 < NK) cpwait<1>(); else cpwait<0>();
        __syncthreads();
        // buffer (kt+2)%3 was last read in iter kt-1; readers passed the barrier.
        if (kt + 2 < NK) load_stage(kt + 2);

        const float* cA = sm + (kt % 3) * ST;
        const float* cB = cA + 128 * 36;

#pragma unroll
        for (int kk = 0; kk < 4; kk++) {
            unsigned af[4][4], bf[4][2];
#pragma unroll
            for (int mt = 0; mt < 4; mt++) {
                const float* p = cA + (wm + mt * 16 + g) * 36 + kk * 8 + tg;
                if (CVT_A) {
                    af[mt][0] = f2tf(p[0]);
                    af[mt][1] = f2tf(p[8 * 36]);
                    af[mt][2] = f2tf(p[4]);
                    af[mt][3] = f2tf(p[8 * 36 + 4]);
                } else {
                    af[mt][0] = __float_as_uint(p[0]);
                    af[mt][1] = __float_as_uint(p[8 * 36]);
                    af[mt][2] = __float_as_uint(p[4]);
                    af[mt][3] = __float_as_uint(p[8 * 36 + 4]);
                }
            }
#pragma unroll
            for (int nt = 0; nt < 4; nt++) {
                const float* p = cB + (wn + nt * 8 + g) * 36 + kk * 8 + tg;
                bf[nt][0] = __float_as_uint(p[0]);
                bf[nt][1] = __float_as_uint(p[4]);
            }
#pragma unroll
            for (int mt = 0; mt < 4; mt++)
#pragma unroll
                for (int nt = 0; nt < 4; nt++)
                    mma8(acc[mt][nt], af[mt], bf[nt]);
        }
    }

    // ---------------- epilogue (float2 stores, no smem) ----------------
    const float Dscale = (EPI == 1) ? g_D : 1.f;
#pragma unroll
    for (int mt = 0; mt < 4; mt++) {
#pragma unroll
        for (int nt = 0; nt < 4; nt++) {
            int cl = wn + nt * 8 + tg * 2;          // col in [0,128)
            int r0 = wm + mt * 16 + g;              // rows r0, r0+8
            float2 v01 = make_float2(acc[mt][nt][0], acc[mt][nt][1]);
            float2 v23 = make_float2(acc[mt][nt][2], acc[mt][nt][3]);
            if (EPI == 0) {
                float2 bb = *(const float2*)(bias + n0 + cl);
                v01.x = fmaxf(v01.x + bb.x, 0.f); v01.y = fmaxf(v01.y + bb.y, 0.f);
                v23.x = fmaxf(v23.x + bb.x, 0.f); v23.y = fmaxf(v23.y + bb.y, 0.f);
                int bx = blockIdx.x;                // 8 n-blocks of 128
                int lc = (bx & 1) * 128 + cl;       // col within 256-seg
                if (bx < 6) {
                    // scratch operands stored tf32-rounded: consumers skip cvt
                    v01.x = f2tf_f(v01.x); v01.y = f2tf_f(v01.y);
                    v23.x = f2tf_f(v23.x); v23.y = f2tf_f(v23.y);
                    float* dst = (bx < 2) ? g_U : ((bx < 4) ? g_V : g_Z);
                    *(float2*)(dst + (size_t)(m0 + r0) * KC + lc) = v01;
                    *(float2*)(dst + (size_t)(m0 + r0 + 8) * KC + lc) = v23;
                } else {
                    *(float2*)(out + (size_t)(m0 + r0) * 512 + 256 + lc) = v01;
                    *(float2*)(out + (size_t)(m0 + r0 + 8) * 512 + 256 + lc) = v23;
                }
            } else {
                v01.x *= Dscale; v01.y *= Dscale; v23.x *= Dscale; v23.y *= Dscale;
                int gc = n0 + cl;
                *(float2*)(out + (size_t)(m0 + r0) * 512 + gc) = v01;
                *(float2*)(out + (size_t)(m0 + r0 + 8) * 512 + gc) = v23;
            }
        }
    }
}

// ---------------- H partials: Hpart[z][j][k] = sum over n-chunk of Z[n,j]*V[n,k] ----------------
__global__ __launch_bounds__(256)
void gemm_tn() {
    extern __shared__ float sm[];
    const int TS = 32 * 132;
    float* sZ[2] = { sm, sm + TS };
    float* sV[2] = { sm + 2 * TS, sm + 3 * TS };

    int k0 = blockIdx.x * 128;
    int j0 = blockIdx.y * 128;
    int nb = blockIdx.z * 1024;
    int tid = threadIdx.x;
    int warp = tid >> 5, lane = tid & 31, g = lane >> 2, tg = lane & 3;
    int wm = (warp >> 2) * 64, wn = (warp & 3) * 32;

    float acc[4][4][4];
#pragma unroll
    for (int i = 0; i < 4; i++)
#pragma unroll
        for (int j = 0; j < 4; j++)
#pragma unroll
            for (int c = 0; c < 4; c++) acc[i][j][c] = 0.f;

    auto load_stage = [&](int s, int it) {
        int r0 = nb + it * 32;
#pragma unroll
        for (int i = 0; i < 4; i++) {
            int vi = tid + i * 256;
            int row = vi >> 5, cv = (vi & 31) * 4;
            cpa16(sZ[s] + row * 132 + cv, g_Z + (size_t)(r0 + row) * KC + j0 + cv);
            cpa16(sV[s] + row * 132 + cv, g_V + (size_t)(r0 + row) * KC + k0 + cv);
        }
        cpcommit();
    };

    const int NK = 32;
    load_stage(0, 0);
    int buf = 0;
    for (int kt = 0; kt < NK; kt++) {
        if (kt + 1 < NK) { load_stage(buf ^ 1, kt + 1); cpwait<1>(); }
        else             { cpwait<0>(); }
        __syncthreads();
        const float* cZ = sZ[buf];
        const float* cV = sV[buf];
#pragma unroll
        for (int kk = 0; kk < 4; kk++) {
            int kb = kk * 8 + tg;
            unsigned af[4][4], bf[4][2];
#pragma unroll
            for (int mt2 = 0; mt2 < 4; mt2++) {
                const float* p = cZ + kb * 132 + wm + mt2 * 16 + g;
                af[mt2][0] = __float_as_uint(p[0]);
                af[mt2][1] = __float_as_uint(p[8]);
                af[mt2][2] = __float_as_uint(p[4 * 132]);
                af[mt2][3] = __float_as_uint(p[4 * 132 + 8]);
            }
#pragma unroll
            for (int nt = 0; nt < 4; nt++) {
                const float* p = cV + kb * 132 + wn + nt * 8 + g;
                bf[nt][0] = __float_as_uint(p[0]);
                bf[nt][1] = __float_as_uint(p[4 * 132]);
            }
#pragma unroll
            for (int mt2 = 0; mt2 < 4; mt2++)
#pragma unroll
                for (int nt = 0; nt < 4; nt++)
                    mma8(acc[mt2][nt], af[mt2], bf[nt]);
        }
        __syncthreads();
        buf ^= 1;
    }

    float* dst = g_Hpart + (size_t)blockIdx.z * (KC * KC);
#pragma unroll
    for (int mt2 = 0; mt2 < 4; mt2++)
#pragma unroll
        for (int nt = 0; nt < 4; nt++)
#pragma unroll
            for (int c = 0; c < 4; c++) {
                int rl = wm + mt2 * 16 + g + ((c >= 2) ? 8 : 0);
                int cl = wn + nt * 8 + tg * 2 + (c & 1);
                dst[(j0 + rl) * KC + (k0 + cl)] = acc[mt2][nt][c];
            }
}

// ---------------- column-sum partials of U and V ----------------
__global__ void colsum_k() {
    const float* src = (blockIdx.y == 0) ? g_U : g_V;
    float* dst = (blockIdx.y == 0) ? g_cspU : g_cspV;
    int j = threadIdx.x;
    int r0 = blockIdx.x * 256;
    float s = 0.f;
    for (int r = 0; r < 256; r++) s += src[(size_t)(r0 + r) * KC + j];
    dst[blockIdx.x * KC + j] = s;
}

// ---------------- per-column dot partial: pdot[j] = su_j * sv_j ----------------
__global__ void sumpart_k() {
    int j = blockIdx.x;
    int t = threadIdx.x;
    float u = g_cspU[t * KC + j];
    float v = g_cspV[t * KC + j];
#pragma unroll
    for (int o = 16; o > 0; o >>= 1) {
        u += __shfl_xor_sync(0xffffffffu, u, o);
        v += __shfl_xor_sync(0xffffffffu, v, o);
    }
    __shared__ float ru[8], rv[8];
    if ((t & 31) == 0) { ru[t >> 5] = u; rv[t >> 5] = v; }
    __syncthreads();
    if (t == 0) {
        float su = 0.f, sv = 0.f;
        for (int w = 0; w < 8; w++) { su += ru[w]; sv += rv[w]; }
        g_pdot[j] = su * sv;
    }
}

// ---------------- scalar D ----------------
__global__ void scalar_k() {
    int t = threadIdx.x;
    float p = g_pdot[t * 8] + g_pdot[t * 8 + 1] + g_pdot[t * 8 + 2] + g_pdot[t * 8 + 3]
            + g_pdot[t * 8 + 4] + g_pdot[t * 8 + 5] + g_pdot[t * 8 + 6] + g_pdot[t * 8 + 7];
#pragma unroll
    for (int o = 16; o > 0; o >>= 1) p += __shfl_xor_sync(0xffffffffu, p, o);
    if (t == 0) g_D = 1.f / (p / (float)NROWS + 1e-6f);
}

// ---------------- reduce H partials (store tf32-rounded) ----------------
__global__ void reduceH_k() {
    int i = blockIdx.x * 256 + threadIdx.x;
    float s = 0.f;
    for (int p = 0; p < 64; p++) s += g_Hpart[(size_t)p * (KC * KC) + i];
    g_H[i] = f2tf_f(s);
}

// ---------------- launcher ----------------
extern "C" void kernel_launch(void* const* d_in, const int* in_sizes, int n_in,
                              void* d_out, int out_size) {
    const float* x = (const float*)d_in[0];
    const float* W = (const float*)d_in[1];
    const float* b = (const float*)d_in[2];
    float* out = (float*)d_out;

    const int SM_NT = 3 * 2 * 128 * 36 * 4;   // 110592 B -> 2 CTAs/SM
    const int SM_TN = 4 * 32 * 132 * 4;       // 67584 B
    cudaFuncSetAttribute(gemm_nt<1024, 1, 0>, cudaFuncAttributeMaxDynamicSharedMemorySize, SM_NT);
    cudaFuncSetAttribute(gemm_nt<256, 0, 1>,  cudaFuncAttributeMaxDynamicSharedMemorySize, SM_NT);
    cudaFuncSetAttribute(gemm_tn,             cudaFuncAttributeMaxDynamicSharedMemorySize, SM_TN);

    // 0) prepass + ncu alignment: gemm1 lands at global launch index 5 (-s 5)
    round_W_k<<<1024, 256>>>(W);
    dummy_k<<<1, 32>>>();
    dummy_k<<<1, 32>>>();
    // 1) tmp = relu(x W^T + b): bx 0..5 -> U/V/Z (tf32-rounded), bx 6..7 -> out[:,256:512]
    gemm_nt<1024, 1, 0><<<dim3(8, 512), 256, SM_NT>>>(x, b, out);
    // 2) column sums of U and V (partials)
    colsum_k<<<dim3(256, 2), 256>>>();
    // 3) per-column dot partials
    sumpart_k<<<256, 256>>>();
    // 4) H = Z^T V partials over 64 n-splits
    gemm_tn<<<dim3(2, 2, 64), 256, SM_TN>>>();
    // 5) D scalar
    scalar_k<<<1, 32>>>();
    // 6) reduce H partials (deterministic order, tf32-rounded)
    reduceH_k<<<256, 256>>>();
    // 7) res = U * H^T * D -> out[:,0:256]
    gemm_nt<256, 0, 1><<<dim3(2, 512), 256, SM_NT>>>(nullptr, nullptr, out);
}

// round 12
// speedup vs baseline: 1.1472x; 1.1472x over previous
#include <cuda_runtime.h>
#include <cuda_fp16.h>
#include <cstdint>

// Problem constants
#define NROWS 65536
#define DDIM  1024
#define KC    256

// ---------------- device scratch (no allocations allowed) ----------------
__device__ float  g_U[(size_t)NROWS * KC];
__device__ float  g_V[(size_t)NROWS * KC];
__device__ float  g_Z[(size_t)NROWS * KC];
__device__ __half g_Wh[(size_t)DDIM * DDIM];   // rn-fp16 W
__device__ __half g_Hh[KC * KC];               // rn-fp16 H/256
__device__ float  g_Hpart[64 * KC * KC];
__device__ float  g_cspU[256 * KC];
__device__ float  g_cspV[256 * KC];
__device__ float  g_pdot[KC];
__device__ float  g_D;

// ---------------- helpers ----------------
__device__ __forceinline__ unsigned f2tf(float f) {
    unsigned u;
    asm("cvt.rna.tf32.f32 %0, %1;" : "=r"(u) : "f"(f));
    return u;
}
__device__ __forceinline__ float f2tf_f(float f) { return __uint_as_float(f2tf(f)); }
// pack two f32 -> f16x2 (lo = first element, hi = second); cvt dst = {hi=a, lo=b}
__device__ __forceinline__ unsigned pack_h2(float lo, float hi) {
    unsigned d;
    asm("cvt.rn.f16x2.f32 %0, %1, %2;" : "=r"(d) : "f"(hi), "f"(lo));
    return d;
}
__device__ __forceinline__ void cpa16(void* s, const void* g) {
    unsigned sa = (unsigned)__cvta_generic_to_shared(s);
    asm volatile("cp.async.cg.shared.global [%0], [%1], 16;" :: "r"(sa), "l"(g));
}
__device__ __forceinline__ void cpcommit() { asm volatile("cp.async.commit_group;"); }
template <int N> __device__ __forceinline__ void cpwait() {
    asm volatile("cp.async.wait_group %0;" :: "n"(N));
}
// fp16 mma, fp32 accumulate
__device__ __forceinline__ void mma16(float* c, const unsigned* a, const unsigned* b) {
    asm volatile(
        "mma.sync.aligned.m16n8k16.row.col.f32.f16.f16.f32 "
        "{%0,%1,%2,%3},{%4,%5,%6,%7},{%8,%9},{%0,%1,%2,%3};"
        : "+f"(c[0]), "+f"(c[1]), "+f"(c[2]), "+f"(c[3])
        : "r"(a[0]), "r"(a[1]), "r"(a[2]), "r"(a[3]), "r"(b[0]), "r"(b[1]));
}
// legacy tf32 mma (gemm_tn path)
__device__ __forceinline__ void mma8(float* c, const unsigned* a, const unsigned* b) {
    asm volatile(
        "mma.sync.aligned.m16n8k8.row.col.f32.tf32.tf32.f32 "
        "{%0,%1,%2,%3},{%4,%5,%6,%7},{%8,%9},{%0,%1,%2,%3};"
        : "+f"(c[0]), "+f"(c[1]), "+f"(c[2]), "+f"(c[3])
        : "r"(a[0]), "r"(a[1]), "r"(a[2]), "r"(a[3]), "r"(b[0]), "r"(b[1]));
}

// ---------------- prepass: W -> rn-fp16 g_Wh ----------------
__global__ void Wh_k(const float* __restrict__ W) {
    int i = (blockIdx.x * 256 + threadIdx.x) * 4;
    float4 v = *(const float4*)(W + i);
    uint2 o;
    o.x = pack_h2(v.x, v.y);
    o.y = pack_h2(v.z, v.w);
    *(uint2*)((char*)g_Wh + (size_t)i * 2) = o;
}
__global__ void dummy_k() {}

// ================= NT GEMM (fp16 mma): C[M,N] = A[M,KA] * B[N,KA]^T =================
// CTA tile 128x128, 8 warps (2x4), warp tile 64x32. K-chunk 32 (2 x K16 mma steps).
// A: fp32 smem (stride 36 floats), fragments via LDS.64 + cvt.rn.f16x2 (rn).
// B: fp16 smem (stride 20 uints, conflict-free), pre-rounded fp16 source.
// 3-stage cp.async, one __syncthreads per K-chunk, 2 CTAs/SM.
// EPI=0: bias+relu; bx 0..1 -> U raw, 2..5 -> V/Z tf32-rounded, 6..7 -> out[:,256:512].
// EPI=1: res = U * (H/256)^T * (g_D*256) -> out[:, 0:256].
template <int KA, int EPI>
__global__ __launch_bounds__(256, 2)
void gemm_nt(const float* __restrict__ Ain, const float* __restrict__ bias,
             float* __restrict__ out) {
    extern __shared__ float sm[];
    const int SAf = 128 * 36;                // A floats per stage
    const int SBu = 128 * 20;                // B uints per stage
    const int STf = SAf + SBu;               // stage size in 4B words

    const float* A  = (EPI == 1) ? g_U : Ain;
    const __half* B = (EPI == 1) ? g_Hh : g_Wh;

    const int m0 = blockIdx.y * 128, n0 = blockIdx.x * 128;
    const int tid = threadIdx.x;
    const int warp = tid >> 5, lane = tid & 31, g = lane >> 2, tg = lane & 3;
    const int wm = (warp >> 2) * 64, wn = (warp & 3) * 32;

    float acc[4][4][4];
#pragma unroll
    for (int i = 0; i < 4; i++)
#pragma unroll
        for (int j = 0; j < 4; j++)
#pragma unroll
            for (int c = 0; c < 4; c++) acc[i][j][c] = 0.f;

    const int NK = KA / 32;

    auto load_stage = [&](int s) {
        float* sA = sm + (s % 3) * STf;
        unsigned* sB = (unsigned*)(sA + SAf);
        const int k0 = s * 32;
#pragma unroll
        for (int i = 0; i < 4; i++) {        // A: 128 rows x 32 floats
            int idx = tid + i * 256;
            int row = idx >> 3, q = idx & 7;
            cpa16(sA + row * 36 + q * 4, A + (size_t)(m0 + row) * KA + k0 + q * 4);
        }
#pragma unroll
        for (int i = 0; i < 2; i++) {        // B: 128 rows x 32 halfs
            int idx = tid + i * 256;
            int row = idx >> 2, q = idx & 3;
            cpa16(sB + row * 20 + q * 4, B + (size_t)(n0 + row) * KA + k0 + q * 8);
        }
        cpcommit();
    };

    load_stage(0);
    load_stage(1);

    for (int kt = 0; kt < NK; kt++) {
        if (kt + 1 < NK) cpwait<1>(); else cpwait<0>();
        __syncthreads();
        // buffer (kt+2)%3 was last read in iter kt-1; readers passed the barrier.
        if (kt + 2 < NK) load_stage(kt + 2);

        const float* cA = sm + (kt % 3) * STf;
        const unsigned* cB = (const unsigned*)(cA + SAf);

#pragma unroll
        for (int kk = 0; kk < 2; kk++) {     // 2 x K16 per K32 chunk
            unsigned af[4][4], bf[4][2];
#pragma unroll
            for (int mt = 0; mt < 4; mt++) {
                const float* pa = cA + (wm + mt * 16 + g) * 36 + kk * 16 + tg * 2;
                float2 v0 = *(const float2*)(pa);            // (g,      k..k+1)
                float2 v1 = *(const float2*)(pa + 8 * 36);   // (g+8,    k..k+1)
                float2 v2 = *(const float2*)(pa + 8);        // (g,   k+8..k+9)
                float2 v3 = *(const float2*)(pa + 8 * 36 + 8);
                af[mt][0] = pack_h2(v0.x, v0.y);
                af[mt][1] = pack_h2(v1.x, v1.y);
                af[mt][2] = pack_h2(v2.x, v2.y);
                af[mt][3] = pack_h2(v3.x, v3.y);
            }
#pragma unroll
            for (int nt = 0; nt < 4; nt++) {
                const unsigned* pb = cB + (wn + nt * 8 + g) * 20 + kk * 8 + tg;
                bf[nt][0] = pb[0];
                bf[nt][1] = pb[4];
            }
#pragma unroll
            for (int mt = 0; mt < 4; mt++)
#pragma unroll
                for (int nt = 0; nt < 4; nt++)
                    mma16(acc[mt][nt], af[mt], bf[nt]);
        }
    }

    // ---------------- epilogue (float2 stores, no smem) ----------------
    const float Dscale = (EPI == 1) ? g_D * 256.f : 1.f;
#pragma unroll
    for (int mt = 0; mt < 4; mt++) {
#pragma unroll
        for (int nt = 0; nt < 4; nt++) {
            int cl = wn + nt * 8 + tg * 2;          // col in [0,128)
            int r0 = wm + mt * 16 + g;              // rows r0, r0+8
            float2 v01 = make_float2(acc[mt][nt][0], acc[mt][nt][1]);
            float2 v23 = make_float2(acc[mt][nt][2], acc[mt][nt][3]);
            if (EPI == 0) {
                float2 bb = *(const float2*)(bias + n0 + cl);
                v01.x = fmaxf(v01.x + bb.x, 0.f); v01.y = fmaxf(v01.y + bb.y, 0.f);
                v23.x = fmaxf(v23.x + bb.x, 0.f); v23.y = fmaxf(v23.y + bb.y, 0.f);
                int bx = blockIdx.x;                // 8 n-blocks of 128
                int lc = (bx & 1) * 128 + cl;       // col within 256-seg
                if (bx < 2) {                       // U: raw fp32 (GEMM3 cvts in-loop)
                    *(float2*)(g_U + (size_t)(m0 + r0) * KC + lc) = v01;
                    *(float2*)(g_U + (size_t)(m0 + r0 + 8) * KC + lc) = v23;
                } else if (bx < 6) {                // V/Z: tf32-rounded for gemm_tn
                    v01.x = f2tf_f(v01.x); v01.y = f2tf_f(v01.y);
                    v23.x = f2tf_f(v23.x); v23.y = f2tf_f(v23.y);
                    float* dst = (bx < 4) ? g_V : g_Z;
                    *(float2*)(dst + (size_t)(m0 + r0) * KC + lc) = v01;
                    *(float2*)(dst + (size_t)(m0 + r0 + 8) * KC + lc) = v23;
                } else {
                    *(float2*)(out + (size_t)(m0 + r0) * 512 + 256 + lc) = v01;
                    *(float2*)(out + (size_t)(m0 + r0 + 8) * 512 + 256 + lc) = v23;
                }
            } else {
                v01.x *= Dscale; v01.y *= Dscale; v23.x *= Dscale; v23.y *= Dscale;
                int gc = n0 + cl;
                *(float2*)(out + (size_t)(m0 + r0) * 512 + gc) = v01;
                *(float2*)(out + (size_t)(m0 + r0 + 8) * 512 + gc) = v23;
            }
        }
    }
}

// ---------------- H partials (tf32 path): Hpart[z][j][k] = sum_nchunk Z[n,j]*V[n,k] ----------------
__global__ __launch_bounds__(256)
void gemm_tn() {
    extern __shared__ float sm[];
    const int TS = 32 * 132;
    float* sZ[2] = { sm, sm + TS };
    float* sV[2] = { sm + 2 * TS, sm + 3 * TS };

    int k0 = blockIdx.x * 128;
    int j0 = blockIdx.y * 128;
    int nb = blockIdx.z * 1024;
    int tid = threadIdx.x;
    int warp = tid >> 5, lane = tid & 31, g = lane >> 2, tg = lane & 3;
    int wm = (warp >> 2) * 64, wn = (warp & 3) * 32;

    float acc[4][4][4];
#pragma unroll
    for (int i = 0; i < 4; i++)
#pragma unroll
        for (int j = 0; j < 4; j++)
#pragma unroll
            for (int c = 0; c < 4; c++) acc[i][j][c] = 0.f;

    auto load_stage = [&](int s, int it) {
        int r0 = nb + it * 32;
#pragma unroll
        for (int i = 0; i < 4; i++) {
            int vi = tid + i * 256;
            int row = vi >> 5, cv = (vi & 31) * 4;
            cpa16(sZ[s] + row * 132 + cv, g_Z + (size_t)(r0 + row) * KC + j0 + cv);
            cpa16(sV[s] + row * 132 + cv, g_V + (size_t)(r0 + row) * KC + k0 + cv);
        }
        cpcommit();
    };

    const int NK = 32;
    load_stage(0, 0);
    int buf = 0;
    for (int kt = 0; kt < NK; kt++) {
        if (kt + 1 < NK) { load_stage(buf ^ 1, kt + 1); cpwait<1>(); }
        else             { cpwait<0>(); }
        __syncthreads();
        const float* cZ = sZ[buf];
        const float* cV = sV[buf];
#pragma unroll
        for (int kk = 0; kk < 4; kk++) {
            int kb = kk * 8 + tg;
            unsigned af[4][4], bf[4][2];
#pragma unroll
            for (int mt2 = 0; mt2 < 4; mt2++) {
                const float* p = cZ + kb * 132 + wm + mt2 * 16 + g;
                af[mt2][0] = __float_as_uint(p[0]);
                af[mt2][1] = __float_as_uint(p[8]);
                af[mt2][2] = __float_as_uint(p[4 * 132]);
                af[mt2][3] = __float_as_uint(p[4 * 132 + 8]);
            }
#pragma unroll
            for (int nt = 0; nt < 4; nt++) {
                const float* p = cV + kb * 132 + wn + nt * 8 + g;
                bf[nt][0] = __float_as_uint(p[0]);
                bf[nt][1] = __float_as_uint(p[4 * 132]);
            }
#pragma unroll
            for (int mt2 = 0; mt2 < 4; mt2++)
#pragma unroll
                for (int nt = 0; nt < 4; nt++)
                    mma8(acc[mt2][nt], af[mt2], bf[nt]);
        }
        __syncthreads();
        buf ^= 1;
    }

    float* dst = g_Hpart + (size_t)blockIdx.z * (KC * KC);
#pragma unroll
    for (int mt2 = 0; mt2 < 4; mt2++)
#pragma unroll
        for (int nt = 0; nt < 4; nt++)
#pragma unroll
            for (int c = 0; c < 4; c++) {
                int rl = wm + mt2 * 16 + g + ((c >= 2) ? 8 : 0);
                int cl = wn + nt * 8 + tg * 2 + (c & 1);
                dst[(j0 + rl) * KC + (k0 + cl)] = acc[mt2][nt][c];
            }
}

// ---------------- column-sum partials of U and V ----------------
__global__ void colsum_k() {
    const float* src = (blockIdx.y == 0) ? g_U : g_V;
    float* dst = (blockIdx.y == 0) ? g_cspU : g_cspV;
    int j = threadIdx.x;
    int r0 = blockIdx.x * 256;
    float s = 0.f;
    for (int r = 0; r < 256; r++) s += src[(size_t)(r0 + r) * KC + j];
    dst[blockIdx.x * KC + j] = s;
}

// ---------------- per-column dot partial: pdot[j] = su_j * sv_j ----------------
__global__ void sumpart_k() {
    int j = blockIdx.x;
    int t = threadIdx.x;
    float u = g_cspU[t * KC + j];
    float v = g_cspV[t * KC + j];
#pragma unroll
    for (int o = 16; o > 0; o >>= 1) {
        u += __shfl_xor_sync(0xffffffffu, u, o);
        v += __shfl_xor_sync(0xffffffffu, v, o);
    }
    __shared__ float ru[8], rv[8];
    if ((t & 31) == 0) { ru[t >> 5] = u; rv[t >> 5] = v; }
    __syncthreads();
    if (t == 0) {
        float su = 0.f, sv = 0.f;
        for (int w = 0; w < 8; w++) { su += ru[w]; sv += rv[w]; }
        g_pdot[j] = su * sv;
    }
}

// ---------------- scalar D ----------------
__global__ void scalar_k() {
    int t = threadIdx.x;
    float p = g_pdot[t * 8] + g_pdot[t * 8 + 1] + g_pdot[t * 8 + 2] + g_pdot[t * 8 + 3]
            + g_pdot[t * 8 + 4] + g_pdot[t * 8 + 5] + g_pdot[t * 8 + 6] + g_pdot[t * 8 + 7];
#pragma unroll
    for (int o = 16; o > 0; o >>= 1) p += __shfl_xor_sync(0xffffffffu, p, o);
    if (t == 0) g_D = 1.f / (p / (float)NROWS + 1e-6f);
}

// ---------------- reduce H partials -> fp16 H/256 ----------------
__global__ void reduceH_k() {
    int i = blockIdx.x * 256 + threadIdx.x;
    float s = 0.f;
    for (int p = 0; p < 64; p++) s += g_Hpart[(size_t)p * (KC * KC) + i];
    g_Hh[i] = __float2half_rn(s * (1.f / 256.f));
}

// ---------------- launcher ----------------
extern "C" void kernel_launch(void* const* d_in, const int* in_sizes, int n_in,
                              void* d_out, int out_size) {
    const float* x = (const float*)d_in[0];
    const float* W = (const float*)d_in[1];
    const float* b = (const float*)d_in[2];
    float* out = (float*)d_out;

    const int SM_NT = 3 * (128 * 36 + 128 * 20) * 4;  // 86016 B -> 2 CTAs/SM
    const int SM_TN = 4 * 32 * 132 * 4;               // 67584 B
    cudaFuncSetAttribute(gemm_nt<1024, 0>, cudaFuncAttributeMaxDynamicSharedMemorySize, SM_NT);
    cudaFuncSetAttribute(gemm_nt<256, 1>,  cudaFuncAttributeMaxDynamicSharedMemorySize, SM_NT);
    cudaFuncSetAttribute(gemm_tn,          cudaFuncAttributeMaxDynamicSharedMemorySize, SM_TN);

    // 0) prepass + ncu alignment: gemm1 lands at global launch index 5 (-s 5)
    Wh_k<<<1024, 256>>>(W);
    dummy_k<<<1, 32>>>();
    dummy_k<<<1, 32>>>();
    // 1) tmp = relu(x W^T + b): bx 0..1 -> U raw, 2..5 -> V/Z tf32, 6..7 -> out[:,256:512]
    gemm_nt<1024, 0><<<dim3(8, 512), 256, SM_NT>>>(x, b, out);
    // 2) column sums of U and V (partials)
    colsum_k<<<dim3(256, 2), 256>>>();
    // 3) per-column dot partials
    sumpart_k<<<256, 256>>>();
    // 4) H = Z^T V partials over 64 n-splits (tf32)
    gemm_tn<<<dim3(2, 2, 64), 256, SM_TN>>>();
    // 5) D scalar
    scalar_k<<<1, 32>>>();
    // 6) reduce H partials -> fp16 H/256 (deterministic order)
    reduceH_k<<<256, 256>>>();
    // 7) res = U * (H/256)^T * (D*256) -> out[:,0:256]
    gemm_nt<256, 1><<<dim3(2, 512), 256, SM_NT>>>(nullptr, nullptr, out);
}

// round 13
// speedup vs baseline: 1.7649x; 1.5383x over previous
#include <cuda_runtime.h>
#include <cuda_fp16.h>
#include <cstdint>

// Problem constants
#define NROWS 65536
#define DDIM  1024
#define KC    256

// ---------------- device scratch (no allocations allowed) ----------------
__device__ __half g_xh[(size_t)NROWS * DDIM];  // rn-fp16 x
__device__ __half g_Uh[(size_t)NROWS * KC];    // rn-fp16 U
__device__ float  g_V[(size_t)NROWS * KC];
__device__ float  g_Z[(size_t)NROWS * KC];
__device__ __half g_Wh[(size_t)DDIM * DDIM];   // rn-fp16 W
__device__ __half g_Hh[KC * KC];               // rn-fp16 H/256
__device__ float  g_Hpart[64 * KC * KC];
__device__ float  g_cspU[256 * KC];
__device__ float  g_cspV[256 * KC];
__device__ float  g_pdot[KC];
__device__ float  g_D;

// ---------------- helpers ----------------
__device__ __forceinline__ unsigned f2tf(float f) {
    unsigned u;
    asm("cvt.rna.tf32.f32 %0, %1;" : "=r"(u) : "f"(f));
    return u;
}
__device__ __forceinline__ float f2tf_f(float f) { return __uint_as_float(f2tf(f)); }
// pack two f32 -> f16x2 (lo = first element, hi = second)
__device__ __forceinline__ unsigned pack_h2(float lo, float hi) {
    unsigned d;
    asm("cvt.rn.f16x2.f32 %0, %1, %2;" : "=r"(d) : "f"(hi), "f"(lo));
    return d;
}
__device__ __forceinline__ unsigned s2u(const void* p) {
    return (unsigned)__cvta_generic_to_shared(p);
}
__device__ __forceinline__ void cpa16(void* s, const void* g) {
    asm volatile("cp.async.cg.shared.global [%0], [%1], 16;" :: "r"(s2u(s)), "l"(g));
}
__device__ __forceinline__ void cpcommit() { asm volatile("cp.async.commit_group;"); }
template <int N> __device__ __forceinline__ void cpwait() {
    asm volatile("cp.async.wait_group %0;" :: "n"(N));
}
__device__ __forceinline__ void ldsm4(unsigned* r, unsigned a) {
    asm volatile("ldmatrix.sync.aligned.m8n8.x4.shared.b16 {%0,%1,%2,%3}, [%4];"
                 : "=r"(r[0]), "=r"(r[1]), "=r"(r[2]), "=r"(r[3]) : "r"(a));
}
__device__ __forceinline__ void ldsm2(unsigned* r, unsigned a) {
    asm volatile("ldmatrix.sync.aligned.m8n8.x2.shared.b16 {%0,%1}, [%2];"
                 : "=r"(r[0]), "=r"(r[1]) : "r"(a));
}
__device__ __forceinline__ void mma16(float* c, const unsigned* a, const unsigned* b) {
    asm volatile(
        "mma.sync.aligned.m16n8k16.row.col.f32.f16.f16.f32 "
        "{%0,%1,%2,%3},{%4,%5,%6,%7},{%8,%9},{%0,%1,%2,%3};"
        : "+f"(c[0]), "+f"(c[1]), "+f"(c[2]), "+f"(c[3])
        : "r"(a[0]), "r"(a[1]), "r"(a[2]), "r"(a[3]), "r"(b[0]), "r"(b[1]));
}
__device__ __forceinline__ void mma8(float* c, const unsigned* a, const unsigned* b) {
    asm volatile(
        "mma.sync.aligned.m16n8k8.row.col.f32.tf32.tf32.f32 "
        "{%0,%1,%2,%3},{%4,%5,%6,%7},{%8,%9},{%0,%1,%2,%3};"
        : "+f"(c[0]), "+f"(c[1]), "+f"(c[2]), "+f"(c[3])
        : "r"(a[0]), "r"(a[1]), "r"(a[2]), "r"(a[3]), "r"(b[0]), "r"(b[1]));
}

// ---------------- prepasses ----------------
__global__ void xh_k(const float* __restrict__ x) {
    size_t i = ((size_t)blockIdx.x * 256 + threadIdx.x) * 4;
    float4 v = *(const float4*)(x + i);
    uint2 o;
    o.x = pack_h2(v.x, v.y);
    o.y = pack_h2(v.z, v.w);
    *(uint2*)((char*)g_xh + i * 2) = o;
}
__global__ void Wh_k(const float* __restrict__ W) {
    int i = (blockIdx.x * 256 + threadIdx.x) * 4;
    float4 v = *(const float4*)(W + i);
    uint2 o;
    o.x = pack_h2(v.x, v.y);
    o.y = pack_h2(v.z, v.w);
    *(uint2*)((char*)g_Wh + (size_t)i * 2) = o;
}
__global__ void dummy_k() {}

// ================= fp16 NT GEMM: C[M,N] = A[M,KA] * B[N,KA]^T =================
// CTA 128x128, 8 warps (2x4), warp tile 64x32. K-chunk 64 (4 x K16 mma).
// A,B fp16 smem, row stride 144B (conflict-free ldmatrix), 3-stage cp.async,
// one __syncthreads per K-chunk, 2 CTAs/SM.
// EPI=0: bias+relu; bx 0..1 -> g_Uh (fp16), 2..5 -> V/Z (tf32-rounded fp32),
//        6..7 -> out[:,256:512].
// EPI=1: res = U * (H/256)^T * (g_D*256) -> out[:, 0:256].
template <int KA, int EPI>
__global__ __launch_bounds__(256, 2)
void gemm_h(const float* __restrict__ bias, float* __restrict__ out) {
    extern __shared__ unsigned smu[];
    const int RS = 36;                       // row stride in uints (144B)
    const int TILE = 128 * RS;               // one operand tile, uints
    const int STu = 2 * TILE;                // stage size, uints

    const __half* A = (EPI == 1) ? g_Uh : g_xh;
    const __half* B = (EPI == 1) ? g_Hh : g_Wh;

    const int m0 = blockIdx.y * 128, n0 = blockIdx.x * 128;
    const int tid = threadIdx.x;
    const int warp = tid >> 5, lane = tid & 31, g = lane >> 2, tg = lane & 3;
    const int wm = (warp >> 2) * 64, wn = (warp & 3) * 32;

    float acc[4][4][4];
#pragma unroll
    for (int i = 0; i < 4; i++)
#pragma unroll
        for (int j = 0; j < 4; j++)
#pragma unroll
            for (int c = 0; c < 4; c++) acc[i][j][c] = 0.f;

    const int NK = KA / 64;

    auto load_stage = [&](int s) {
        unsigned* sA = smu + (s % 3) * STu;
        unsigned* sB = sA + TILE;
        const int k0 = s * 64;
#pragma unroll
        for (int i = 0; i < 4; i++) {        // A: 128 rows x 64 halfs (8x16B/row)
            int idx = tid + i * 256;
            int row = idx >> 3, q = idx & 7;
            cpa16(sA + row * RS + q * 4, A + (size_t)(m0 + row) * KA + k0 + q * 8);
        }
#pragma unroll
        for (int i = 0; i < 4; i++) {        // B: 128 rows x 64 halfs
            int idx = tid + i * 256;
            int row = idx >> 3, q = idx & 7;
            cpa16(sB + row * RS + q * 4, B + (size_t)(n0 + row) * KA + k0 + q * 8);
        }
        cpcommit();
    };

    // ldmatrix per-thread address components
    const int a_row = lane & 15;
    const int a_koff = ((lane >> 4) & 1) * 16;
    const int b_row = lane & 7;
    const int b_koff = ((lane >> 3) & 1) * 16;

    load_stage(0);
    load_stage(1);

    for (int kt = 0; kt < NK; kt++) {
        if (kt + 1 < NK) cpwait<1>(); else cpwait<0>();
        __syncthreads();
        // buffer (kt+2)%3 was last read in iter kt-1; readers passed the barrier.
        if (kt + 2 < NK) load_stage(kt + 2);

        const unsigned aA = s2u(smu + (kt % 3) * STu);
        const unsigned aB = aA + TILE * 4;

#pragma unroll
        for (int kk = 0; kk < 4; kk++) {     // 4 x K16 per K64 chunk
            unsigned af[4][4], bf[4][2];
#pragma unroll
            for (int mt = 0; mt < 4; mt++)
                ldsm4(af[mt], aA + (unsigned)((wm + mt * 16 + a_row) * 144 + kk * 32 + a_koff));
#pragma unroll
            for (int nt = 0; nt < 4; nt++)
                ldsm2(bf[nt], aB + (unsigned)((wn + nt * 8 + b_row) * 144 + kk * 32 + b_koff));
#pragma unroll
            for (int mt = 0; mt < 4; mt++)
#pragma unroll
                for (int nt = 0; nt < 4; nt++)
                    mma16(acc[mt][nt], af[mt], bf[nt]);
        }
    }

    // ---------------- epilogue ----------------
    const float Dscale = (EPI == 1) ? g_D * 256.f : 1.f;
#pragma unroll
    for (int mt = 0; mt < 4; mt++) {
#pragma unroll
        for (int nt = 0; nt < 4; nt++) {
            int cl = wn + nt * 8 + tg * 2;          // col in [0,128)
            int r0 = wm + mt * 16 + g;              // rows r0, r0+8
            float2 v01 = make_float2(acc[mt][nt][0], acc[mt][nt][1]);
            float2 v23 = make_float2(acc[mt][nt][2], acc[mt][nt][3]);
            if (EPI == 0) {
                float2 bb = *(const float2*)(bias + n0 + cl);
                v01.x = fmaxf(v01.x + bb.x, 0.f); v01.y = fmaxf(v01.y + bb.y, 0.f);
                v23.x = fmaxf(v23.x + bb.x, 0.f); v23.y = fmaxf(v23.y + bb.y, 0.f);
                int bx = blockIdx.x;                // 8 n-blocks of 128
                int lc = (bx & 1) * 128 + cl;       // col within 256-seg
                if (bx < 2) {                       // U -> fp16 (GEMM3 operand)
                    *(unsigned*)((char*)g_Uh + ((size_t)(m0 + r0) * KC + lc) * 2) =
                        pack_h2(v01.x, v01.y);
                    *(unsigned*)((char*)g_Uh + ((size_t)(m0 + r0 + 8) * KC + lc) * 2) =
                        pack_h2(v23.x, v23.y);
                } else if (bx < 6) {                // V/Z: tf32-rounded for gemm_tn
                    v01.x = f2tf_f(v01.x); v01.y = f2tf_f(v01.y);
                    v23.x = f2tf_f(v23.x); v23.y = f2tf_f(v23.y);
                    float* dst = (bx < 4) ? g_V : g_Z;
                    *(float2*)(dst + (size_t)(m0 + r0) * KC + lc) = v01;
                    *(float2*)(dst + (size_t)(m0 + r0 + 8) * KC + lc) = v23;
                } else {
                    *(float2*)(out + (size_t)(m0 + r0) * 512 + 256 + lc) = v01;
                    *(float2*)(out + (size_t)(m0 + r0 + 8) * 512 + 256 + lc) = v23;
                }
            } else {
                v01.x *= Dscale; v01.y *= Dscale; v23.x *= Dscale; v23.y *= Dscale;
                int gc = n0 + cl;
                *(float2*)(out + (size_t)(m0 + r0) * 512 + gc) = v01;
                *(float2*)(out + (size_t)(m0 + r0 + 8) * 512 + gc) = v23;
            }
        }
    }
}

// ---------------- H partials (tf32 path): Hpart[z][j][k] = sum_nchunk Z[n,j]*V[n,k] ----------------
__global__ __launch_bounds__(256)
void gemm_tn() {
    extern __shared__ float sm[];
    const int TS = 32 * 132;
    float* sZ[2] = { sm, sm + TS };
    float* sV[2] = { sm + 2 * TS, sm + 3 * TS };

    int k0 = blockIdx.x * 128;
    int j0 = blockIdx.y * 128;
    int nb = blockIdx.z * 1024;
    int tid = threadIdx.x;
    int warp = tid >> 5, lane = tid & 31, g = lane >> 2, tg = lane & 3;
    int wm = (warp >> 2) * 64, wn = (warp & 3) * 32;

    float acc[4][4][4];
#pragma unroll
    for (int i = 0; i < 4; i++)
#pragma unroll
        for (int j = 0; j < 4; j++)
#pragma unroll
            for (int c = 0; c < 4; c++) acc[i][j][c] = 0.f;

    auto load_stage = [&](int s, int it) {
        int r0 = nb + it * 32;
#pragma unroll
        for (int i = 0; i < 4; i++) {
            int vi = tid + i * 256;
            int row = vi >> 5, cv = (vi & 31) * 4;
            cpa16(sZ[s] + row * 132 + cv, g_Z + (size_t)(r0 + row) * KC + j0 + cv);
            cpa16(sV[s] + row * 132 + cv, g_V + (size_t)(r0 + row) * KC + k0 + cv);
        }
        cpcommit();
    };

    const int NK = 32;
    load_stage(0, 0);
    int buf = 0;
    for (int kt = 0; kt < NK; kt++) {
        if (kt + 1 < NK) { load_stage(buf ^ 1, kt + 1); cpwait<1>(); }
        else             { cpwait<0>(); }
        __syncthreads();
        const float* cZ = sZ[buf];
        const float* cV = sV[buf];
#pragma unroll
        for (int kk = 0; kk < 4; kk++) {
            int kb = kk * 8 + tg;
            unsigned af[4][4], bf[4][2];
#pragma unroll
            for (int mt2 = 0; mt2 < 4; mt2++) {
                const float* p = cZ + kb * 132 + wm + mt2 * 16 + g;
                af[mt2][0] = __float_as_uint(p[0]);
                af[mt2][1] = __float_as_uint(p[8]);
                af[mt2][2] = __float_as_uint(p[4 * 132]);
                af[mt2][3] = __float_as_uint(p[4 * 132 + 8]);
            }
#pragma unroll
            for (int nt = 0; nt < 4; nt++) {
                const float* p = cV + kb * 132 + wn + nt * 8 + g;
                bf[nt][0] = __float_as_uint(p[0]);
                bf[nt][1] = __float_as_uint(p[4 * 132]);
            }
#pragma unroll
            for (int mt2 = 0; mt2 < 4; mt2++)
#pragma unroll
                for (int nt = 0; nt < 4; nt++)
                    mma8(acc[mt2][nt], af[mt2], bf[nt]);
        }
        __syncthreads();
        buf ^= 1;
    }

    float* dst = g_Hpart + (size_t)blockIdx.z * (KC * KC);
#pragma unroll
    for (int mt2 = 0; mt2 < 4; mt2++)
#pragma unroll
        for (int nt = 0; nt < 4; nt++)
#pragma unroll
            for (int c = 0; c < 4; c++) {
                int rl = wm + mt2 * 16 + g + ((c >= 2) ? 8 : 0);
                int cl = wn + nt * 8 + tg * 2 + (c & 1);
                dst[(j0 + rl) * KC + (k0 + cl)] = acc[mt2][nt][c];
            }
}

// ---------------- column-sum partials (U fp16, V fp32) ----------------
__global__ void colsum_k() {
    int j = threadIdx.x;
    int r0 = blockIdx.x * 256;
    float s = 0.f;
    if (blockIdx.y == 0) {
        for (int r = 0; r < 256; r++) s += __half2float(g_Uh[(size_t)(r0 + r) * KC + j]);
        g_cspU[blockIdx.x * KC + j] = s;
    } else {
        for (int r = 0; r < 256; r++) s += g_V[(size_t)(r0 + r) * KC + j];
        g_cspV[blockIdx.x * KC + j] = s;
    }
}

// ---------------- per-column dot partial: pdot[j] = su_j * sv_j ----------------
__global__ void sumpart_k() {
    int j = blockIdx.x;
    int t = threadIdx.x;
    float u = g_cspU[t * KC + j];
    float v = g_cspV[t * KC + j];
#pragma unroll
    for (int o = 16; o > 0; o >>= 1) {
        u += __shfl_xor_sync(0xffffffffu, u, o);
        v += __shfl_xor_sync(0xffffffffu, v, o);
    }
    __shared__ float ru[8], rv[8];
    if ((t & 31) == 0) { ru[t >> 5] = u; rv[t >> 5] = v; }
    __syncthreads();
    if (t == 0) {
        float su = 0.f, sv = 0.f;
        for (int w = 0; w < 8; w++) { su += ru[w]; sv += rv[w]; }
        g_pdot[j] = su * sv;
    }
}

// ---------------- scalar D ----------------
__global__ void scalar_k() {
    int t = threadIdx.x;
    float p = g_pdot[t * 8] + g_pdot[t * 8 + 1] + g_pdot[t * 8 + 2] + g_pdot[t * 8 + 3]
            + g_pdot[t * 8 + 4] + g_pdot[t * 8 + 5] + g_pdot[t * 8 + 6] + g_pdot[t * 8 + 7];
#pragma unroll
    for (int o = 16; o > 0; o >>= 1) p += __shfl_xor_sync(0xffffffffu, p, o);
    if (t == 0) g_D = 1.f / (p / (float)NROWS + 1e-6f);
}

// ---------------- reduce H partials -> fp16 H/256 ----------------
__global__ void reduceH_k() {
    int i = blockIdx.x * 256 + threadIdx.x;
    float s = 0.f;
    for (int p = 0; p < 64; p++) s += g_Hpart[(size_t)p * (KC * KC) + i];
    g_Hh[i] = __float2half_rn(s * (1.f / 256.f));
}

// ---------------- launcher ----------------
extern "C" void kernel_launch(void* const* d_in, const int* in_sizes, int n_in,
                              void* d_out, int out_size) {
    const float* x = (const float*)d_in[0];
    const float* W = (const float*)d_in[1];
    const float* b = (const float*)d_in[2];
    float* out = (float*)d_out;

    const int SM_H  = 3 * 2 * 128 * 36 * 4;   // 110592 B -> 2 CTAs/SM
    const int SM_TN = 4 * 32 * 132 * 4;       // 67584 B
    cudaFuncSetAttribute(gemm_h<1024, 0>, cudaFuncAttributeMaxDynamicSharedMemorySize, SM_H);
    cudaFuncSetAttribute(gemm_h<256, 1>,  cudaFuncAttributeMaxDynamicSharedMemorySize, SM_H);
    cudaFuncSetAttribute(gemm_tn,         cudaFuncAttributeMaxDynamicSharedMemorySize, SM_TN);

    // 0) prepasses + ncu alignment: gemm1 lands at global launch index 5 (-s 5)
    xh_k<<<NROWS * DDIM / 1024, 256>>>(x);
    Wh_k<<<1024, 256>>>(W);
    dummy_k<<<1, 32>>>();
    // 1) tmp = relu(x W^T + b): bx 0..1 -> Uh, 2..5 -> V/Z, 6..7 -> out[:,256:512]
    gemm_h<1024, 0><<<dim3(8, 512), 256, SM_H>>>(b, out);
    // 2) column sums of U and V (partials)
    colsum_k<<<dim3(256, 2), 256>>>();
    // 3) per-column dot partials
    sumpart_k<<<256, 256>>>();
    // 4) H = Z^T V partials over 64 n-splits (tf32)
    gemm_tn<<<dim3(2, 2, 64), 256, SM_TN>>>();
    // 5) D scalar
    scalar_k<<<1, 32>>>();
    // 6) reduce H partials -> fp16 H/256 (deterministic order)
    reduceH_k<<<256, 256>>>();
    // 7) res = U * (H/256)^T * (D*256) -> out[:,0:256]
    gemm_h<256, 1><<<dim3(2, 512), 256, SM_H>>>(nullptr, out);
}